// round 1
// baseline (speedup 1.0000x reference)
#include <cuda_runtime.h>
#include <math.h>

typedef unsigned long long ull;

// ---------------- f32x2 packed-math helpers (FFMA2: 2x fp32 FMA throughput) ----
__device__ __forceinline__ ull pack2(float lo, float hi) {
    ull r; asm("mov.b64 %0, {%1, %2};" : "=l"(r) : "f"(lo), "f"(hi)); return r;
}
__device__ __forceinline__ void unpack2(ull v, float& lo, float& hi) {
    asm("mov.b64 {%0, %1}, %2;" : "=f"(lo), "=f"(hi) : "l"(v));
}
__device__ __forceinline__ void fma2(ull& d, ull a, ull b) {
    asm("fma.rn.f32x2 %0, %1, %2, %0;" : "+l"(d) : "l"(a), "l"(b));
}
__device__ __forceinline__ ull mul2(ull a, ull b) {
    ull r; asm("mul.rn.f32x2 %0, %1, %2;" : "=l"(r) : "l"(a), "l"(b)); return r;
}
__device__ __forceinline__ ull add2(ull a, ull b) {
    ull r; asm("add.rn.f32x2 %0, %1, %2;" : "=l"(r) : "l"(a), "l"(b)); return r;
}

// ---------------- problem constants -------------------------------------------
#define BB 8
#define CC 64
#define HC 32
#define NN 4096          // 64*64

// ---------------- device scratch (no cudaMalloc allowed) ----------------------
__device__ float g_xq[BB * CC * NN];     // fake-quantized input, [b][c][n]
__device__ float g_q[BB * NN * HC];      // [b][n][hc]
__device__ float g_k[BB * NN * HC];
__device__ float g_v[BB * NN * HC];
__device__ float g_z[BB * NN * HC];      // attention output, [b][n][hc]
__device__ float g_wqt[CC * HC];         // quantized weights, transposed [c][hc]
__device__ float g_wkt[CC * HC];
__device__ float g_wvt[CC * HC];
__device__ float g_wpq[CC * HC];         // wp quantized, [c_out][hc]

// ---------------- kernel A: per-tensor weight fake-quant ----------------------
__global__ void k_wquant(const float* __restrict__ wq, const float* __restrict__ wk,
                         const float* __restrict__ wv, const float* __restrict__ wp) {
    __shared__ float red[1024];
    int t = threadIdx.x;
    int m = t >> 8;           // matrix id 0..3
    int lt = t & 255;
    const float* src = (m == 0) ? wq : (m == 1) ? wk : (m == 2) ? wv : wp;
    float mx = 0.f;
#pragma unroll
    for (int i = 0; i < 8; i++) mx = fmaxf(mx, fabsf(src[lt + 256 * i]));
    red[t] = mx;
    __syncthreads();
    for (int s = 128; s > 0; s >>= 1) {
        if (lt < s) red[t] = fmaxf(red[t], red[t + s]);
        __syncthreads();
    }
    float scale = red[m << 8] / 127.0f;
#pragma unroll
    for (int i = 0; i < 8; i++) {
        int idx = lt + 256 * i;
        float w = src[idx];
        float q = rintf(w / scale);
        q = fminf(fmaxf(q, -127.f), 127.f);
        float val = q * scale;
        if (m == 3) {
            g_wpq[idx] = val;                   // wp: [c_out][hc] kept row-major
        } else {
            int hc = idx >> 6, c = idx & 63;    // w: [hc][c] -> store [c][hc]
            float* dst = (m == 0) ? g_wqt : (m == 1) ? g_wkt : g_wvt;
            dst[c * HC + hc] = val;
        }
    }
}

// ---------------- kernel B: x fake-quant + fused QKV projections --------------
// grid (32, 8) = (n-tile, batch), 128 threads, one pixel per thread.
__global__ void __launch_bounds__(128) k_xq_qkv(const float* __restrict__ x,
                                                const float* __restrict__ bq,
                                                const float* __restrict__ bk,
                                                const float* __restrict__ bv,
                                                const float* __restrict__ s_in_p) {
    extern __shared__ float smB[];
    float* xs = smB;                 // [64][128]
    float* ws = smB + CC * 128;      // [64][96]  (wq|wk|wv transposed rows)
    const int t = threadIdx.x;
    const int b = blockIdx.y;
    const int n0 = blockIdx.x * 128;
    const float si = s_in_p[0];

    const float* xb = x + ((size_t)b * CC) * NN + n0;
    float* xqb = g_xq + ((size_t)b * CC) * NN + n0;
#pragma unroll 4
    for (int c = 0; c < CC; c++) {
        float v = xb[c * NN + t];
        float r = rintf(v / si);
        r = fminf(fmaxf(r, -128.f), 127.f);
        float q = r * si;
        xqb[c * NN + t] = q;
        xs[c * 128 + t] = q;
    }
    for (int idx = t; idx < CC * 96; idx += 128) {
        int c = idx / 96, j = idx % 96;
        float v = (j < 32) ? g_wqt[c * 32 + j]
                : (j < 64) ? g_wkt[c * 32 + j - 32]
                           : g_wvt[c * 32 + j - 64];
        ws[c * 96 + j] = v;
    }
    __syncthreads();

    ull aq[16], ak[16], av[16];
#pragma unroll
    for (int h = 0; h < 16; h++) {
        aq[h] = pack2(bq[2 * h], bq[2 * h + 1]);
        ak[h] = pack2(bk[2 * h], bk[2 * h + 1]);
        av[h] = pack2(bv[2 * h], bv[2 * h + 1]);
    }
#pragma unroll 2
    for (int c = 0; c < CC; c++) {
        float xv = xs[c * 128 + t];
        ull xp = pack2(xv, xv);
        const ulonglong2* wr = (const ulonglong2*)(ws + c * 96);
#pragma unroll
        for (int j = 0; j < 8; j++) {
            ulonglong2 u = wr[j];
            fma2(aq[2 * j], xp, u.x);
            fma2(aq[2 * j + 1], xp, u.y);
        }
#pragma unroll
        for (int j = 0; j < 8; j++) {
            ulonglong2 u = wr[8 + j];
            fma2(ak[2 * j], xp, u.x);
            fma2(ak[2 * j + 1], xp, u.y);
        }
#pragma unroll
        for (int j = 0; j < 8; j++) {
            ulonglong2 u = wr[16 + j];
            fma2(av[2 * j], xp, u.x);
            fma2(av[2 * j + 1], xp, u.y);
        }
    }
    size_t bn = (size_t)b * NN + n0 + t;
    ulonglong2* qo = (ulonglong2*)(g_q + bn * HC);
    ulonglong2* ko = (ulonglong2*)(g_k + bn * HC);
    ulonglong2* vo = (ulonglong2*)(g_v + bn * HC);
#pragma unroll
    for (int j = 0; j < 8; j++) {
        ulonglong2 u; u.x = aq[2 * j]; u.y = aq[2 * j + 1]; qo[j] = u;
        ulonglong2 w; w.x = ak[2 * j]; w.y = ak[2 * j + 1]; ko[j] = w;
        ulonglong2 z; z.x = av[2 * j]; z.y = av[2 * j + 1]; vo[j] = z;
    }
}

// ---------------- kernel C: flash attention ------------------------------------
// grid (32, 8) = (q-tile of 128 rows, batch), 256 threads, TK=128.
// smem: Qs[32][132] Ks[32][132] Vs[128][32] Ps[128][133] scs[128] lis[128]
#define QS_OFF 0
#define KS_OFF (32 * 132)
#define VS_OFF (KS_OFF + 32 * 132)
#define PS_OFF (VS_OFF + 128 * 32)
#define SC_OFF (PS_OFF + 128 * 133)
#define LI_OFF (SC_OFF + 128)
#define ATTN_SMEM ((LI_OFF + 128) * 4)

__global__ void __launch_bounds__(256, 1) k_attn() {
    extern __shared__ float sm[];
    float* Qs = sm + QS_OFF;
    float* Ks = sm + KS_OFF;
    float* Vs = sm + VS_OFF;
    float* Ps = sm + PS_OFF;
    float* scs = sm + SC_OFF;
    float* lis = sm + LI_OFF;

    const int t = threadIdx.x;
    const int b = blockIdx.y, qt = blockIdx.x;
    const float* Qg = g_q + (((size_t)b * NN) + qt * 128) * HC;
    const float* Kg = g_k + ((size_t)b * NN) * HC;
    const float* Vg = g_v + ((size_t)b * NN) * HC;

    const int ty = t >> 4, tx = t & 15;         // S-phase: rows 8*ty, cols 8*tx
    const int half = t >> 7, lt = t & 127;      // PV split-k halves
    const int ty2 = lt >> 3, tx2 = lt & 7;      // PV: rows 8*ty2, cols 4*tx2

    // Load Q transposed: Qs[d][r]
    for (int idx = t; idx < 128 * HC; idx += 256) {
        int r = idx >> 5, d = idx & 31;
        Qs[d * 132 + r] = Qg[idx];
    }

    float m_r[8], l_r[8];
    ull o2[8][2];
#pragma unroll
    for (int i = 0; i < 8; i++) {
        m_r[i] = -INFINITY; l_r[i] = 0.f;
        o2[i][0] = 0ull; o2[i][1] = 0ull;
    }

    for (int kt = 0; kt < 32; kt++) {
        __syncthreads();   // protect Ks/Vs/Ps from previous iteration readers
        const float* Kt = Kg + kt * 128 * HC;
        const float* Vt = Vg + kt * 128 * HC;
        for (int idx = t; idx < 128 * HC; idx += 256) {
            int r = idx >> 5, d = idx & 31;
            Ks[d * 132 + r] = Kt[idx];
        }
        {
            const float4* v4 = (const float4*)Vt;
            float4* s4 = (float4*)Vs;
#pragma unroll
            for (int i = 0; i < 4; i++) s4[t + 256 * i] = v4[t + 256 * i];
        }
        __syncthreads();

        // ---- S = Q * K^T, 8x8 per thread, f32x2 packed along key cols ----
        ull s2[8][4];
#pragma unroll
        for (int i = 0; i < 8; i++)
#pragma unroll
            for (int j = 0; j < 4; j++) s2[i][j] = 0ull;

        const float* qbase = Qs + 8 * ty;
        const float* kbase = Ks + 8 * tx;
#pragma unroll 8
        for (int d = 0; d < 32; d++) {
            float4 qa = *(const float4*)(qbase + d * 132);
            float4 qb = *(const float4*)(qbase + d * 132 + 4);
            ulonglong2 ka = *(const ulonglong2*)(kbase + d * 132);
            ulonglong2 kb = *(const ulonglong2*)(kbase + d * 132 + 4);
            ull qp[8];
            qp[0] = pack2(qa.x, qa.x); qp[1] = pack2(qa.y, qa.y);
            qp[2] = pack2(qa.z, qa.z); qp[3] = pack2(qa.w, qa.w);
            qp[4] = pack2(qb.x, qb.x); qp[5] = pack2(qb.y, qb.y);
            qp[6] = pack2(qb.z, qb.z); qp[7] = pack2(qb.w, qb.w);
#pragma unroll
            for (int i = 0; i < 8; i++) {
                fma2(s2[i][0], qp[i], ka.x);
                fma2(s2[i][1], qp[i], ka.y);
                fma2(s2[i][2], qp[i], kb.x);
                fma2(s2[i][3], qp[i], kb.y);
            }
        }

        // ---- online softmax (row stats reduced over the 16 tx lanes) ----
#pragma unroll
        for (int i = 0; i < 8; i++) {
            float sv[8];
            unpack2(s2[i][0], sv[0], sv[1]);
            unpack2(s2[i][1], sv[2], sv[3]);
            unpack2(s2[i][2], sv[4], sv[5]);
            unpack2(s2[i][3], sv[6], sv[7]);
            float mx = sv[0];
#pragma unroll
            for (int j = 1; j < 8; j++) mx = fmaxf(mx, sv[j]);
            mx = fmaxf(mx, __shfl_xor_sync(0xffffffffu, mx, 1));
            mx = fmaxf(mx, __shfl_xor_sync(0xffffffffu, mx, 2));
            mx = fmaxf(mx, __shfl_xor_sync(0xffffffffu, mx, 4));
            mx = fmaxf(mx, __shfl_xor_sync(0xffffffffu, mx, 8));
            float mnew = fmaxf(m_r[i], mx);
            float sc = __expf(m_r[i] - mnew);
            m_r[i] = mnew;
            float rs = 0.f;
            float* prow = Ps + (8 * ty + i) * 133 + 8 * tx;
#pragma unroll
            for (int j = 0; j < 8; j++) {
                float e = __expf(sv[j] - mnew);
                prow[j] = e;
                rs += e;
            }
            rs += __shfl_xor_sync(0xffffffffu, rs, 1);
            rs += __shfl_xor_sync(0xffffffffu, rs, 2);
            rs += __shfl_xor_sync(0xffffffffu, rs, 4);
            rs += __shfl_xor_sync(0xffffffffu, rs, 8);
            l_r[i] = l_r[i] * sc + rs;
            if (tx == 0) scs[8 * ty + i] = sc;
        }
        __syncthreads();

        // ---- O = O*scale + P * V, split-k across two 128-thread halves ----
#pragma unroll
        for (int i = 0; i < 8; i++) {
            float sc = scs[8 * ty2 + i];
            ull sp = pack2(sc, sc);
            o2[i][0] = mul2(o2[i][0], sp);
            o2[i][1] = mul2(o2[i][1], sp);
        }
        const float* vbase = Vs + 4 * tx2 + half * 64 * 32;
        const float* pbase = Ps + (8 * ty2) * 133 + half * 64;
#pragma unroll 4
        for (int k = 0; k < 64; k++) {
            ulonglong2 vv = *(const ulonglong2*)(vbase + k * 32);
#pragma unroll
            for (int i = 0; i < 8; i++) {
                float pv = pbase[i * 133 + k];
                ull pp = pack2(pv, pv);
                fma2(o2[i][0], pp, vv.x);
                fma2(o2[i][1], pp, vv.y);
            }
        }
    }

    if (tx == 0) {
#pragma unroll
        for (int i = 0; i < 8; i++) lis[8 * ty + i] = 1.f / l_r[i];
    }
    __syncthreads();
    if (half == 1) {   // spill half-1 partial O into Vs (now free)
#pragma unroll
        for (int i = 0; i < 8; i++) {
            ulonglong2 v; v.x = o2[i][0]; v.y = o2[i][1];
            *(ulonglong2*)(Vs + (8 * ty2 + i) * 32 + 4 * tx2) = v;
        }
    }
    __syncthreads();
    if (half == 0) {   // combine, normalize, store Z
        float* Zg = g_z + (((size_t)b * NN) + qt * 128) * HC;
#pragma unroll
        for (int i = 0; i < 8; i++) {
            int r = 8 * ty2 + i;
            ulonglong2 v = *(const ulonglong2*)(Vs + r * 32 + 4 * tx2);
            ull a0 = add2(o2[i][0], v.x);
            ull a1 = add2(o2[i][1], v.y);
            float li = lis[r];
            ull lp = pack2(li, li);
            a0 = mul2(a0, lp);
            a1 = mul2(a1, lp);
            ulonglong2 w; w.x = a0; w.y = a1;
            *(ulonglong2*)(Zg + r * HC + 4 * tx2) = w;
        }
    }
}

// ---------------- kernel D: z fake-quant + output proj + residual + out fq ----
__global__ void __launch_bounds__(128) k_proj(const float* __restrict__ bp,
                                              const float* __restrict__ s_in_p,
                                              const float* __restrict__ s_out_p,
                                              float* __restrict__ out) {
    __shared__ __align__(16) float zs[HC * 129];
    __shared__ __align__(16) float wsp[CC * HC];
    const int t = threadIdx.x;
    const int b = blockIdx.y;
    const int n0 = blockIdx.x * 128;
    const float si = s_in_p[0];
    const float so = s_out_p[0];

    const float* zb = g_z + (((size_t)b * NN) + n0) * HC;
    for (int idx = t; idx < 128 * HC; idx += 128) {
        int p = idx >> 5, hc = idx & 31;
        float v = zb[idx];
        float r = rintf(v / si);
        r = fminf(fmaxf(r, -128.f), 127.f);
        zs[hc * 129 + p] = r * si;
    }
    for (int idx = t; idx < CC * HC; idx += 128) wsp[idx] = g_wpq[idx];
    __syncthreads();

    ull zp[16];
#pragma unroll
    for (int h = 0; h < 16; h++)
        zp[h] = pack2(zs[(2 * h) * 129 + t], zs[(2 * h + 1) * 129 + t]);

    const float* xqb = g_xq + ((size_t)b * CC) * NN + n0 + t;
    float* ob = out + ((size_t)b * CC) * NN + n0 + t;
#pragma unroll 2
    for (int c0 = 0; c0 < CC; c0++) {
        ull acc0 = 0ull, acc1 = 0ull;
        const ulonglong2* wr = (const ulonglong2*)(wsp + c0 * HC);
#pragma unroll
        for (int j = 0; j < 8; j++) {
            ulonglong2 u = wr[j];
            fma2(acc0, zp[2 * j], u.x);
            fma2(acc1, zp[2 * j + 1], u.y);
        }
        float a, bv2, c, d;
        unpack2(acc0, a, bv2);
        unpack2(acc1, c, d);
        float val = xqb[c0 * NN] + (a + bv2) + (c + d) + bp[c0];
        float r = rintf(val / so);
        r = fminf(fmaxf(r, -128.f), 127.f);
        ob[c0 * NN] = r * so;
    }
}

// ---------------- launch --------------------------------------------------------
extern "C" void kernel_launch(void* const* d_in, const int* in_sizes, int n_in,
                              void* d_out, int out_size) {
    const float* x     = (const float*)d_in[0];
    const float* wq    = (const float*)d_in[1];
    const float* bq    = (const float*)d_in[2];
    const float* wk    = (const float*)d_in[3];
    const float* bk    = (const float*)d_in[4];
    const float* wv    = (const float*)d_in[5];
    const float* bv    = (const float*)d_in[6];
    const float* wp    = (const float*)d_in[7];
    const float* bp    = (const float*)d_in[8];
    const float* s_in  = (const float*)d_in[9];
    const float* s_out = (const float*)d_in[10];
    float* out = (float*)d_out;

    cudaFuncSetAttribute(k_attn, cudaFuncAttributeMaxDynamicSharedMemorySize, ATTN_SMEM);
    cudaFuncSetAttribute(k_xq_qkv, cudaFuncAttributeMaxDynamicSharedMemorySize,
                         (CC * 128 + CC * 96) * 4);

    k_wquant<<<1, 1024>>>(wq, wk, wv, wp);
    k_xq_qkv<<<dim3(32, 8), 128, (CC * 128 + CC * 96) * 4>>>(x, bq, bk, bv, s_in);
    k_attn<<<dim3(32, 8), 256, ATTN_SMEM>>>();
    k_proj<<<dim3(32, 8), 128>>>(bp, s_in, s_out, out);
}